// round 8
// baseline (speedup 1.0000x reference)
#include <cuda_runtime.h>

#define NN 19
#define PP 361
#define BB 16
#define HH 8
#define BPTOT (BB*PP)            // 5776
#define NQ (BPTOT*2)             // 11552
#define LN_EPS 1e-5f
#define INV_SQRT_HD 0.1767766952966369f   // 1/sqrt(32)

// ---------------- scratch: device globals ----------------
__device__ float d_XQKV[BPTOT*768];                   // [bp][xq|xk|xv]
__device__ float d_YV[(size_t)BPTOT*2048];            // [bp][h][256]
__device__ float d_E2[(size_t)BPTOT*NN*256];          // [bp][n][256] (slist rows valid)
__device__ float d_Q2[(size_t)NQ*256];
__device__ float d_K2s[(size_t)BPTOT*8*256];          // gathered keys (with bias)
__device__ float d_V2s[(size_t)BPTOT*8*256];          // gathered values (with bias)
__device__ float d_att[(size_t)NQ*256];
__device__ float d_Z2[(size_t)NQ*256];
__device__ float d_cvec[256];
__device__ int d_deg[NN];
__device__ int d_nbrs[NN][8];
__device__ int d_mlist[PP][8];
__device__ int d_qdeg[PP][2];
__device__ int d_qslot[PP][2][4];
__device__ int d_scnt[PP];
__device__ int d_slist[PP][12];
__device__ int d_rowq[NQ];
__device__ int d_rowm[BPTOT*8];

// ---------------- fused setup ----------------
__global__ void __launch_bounds__(256) k_setup(
    const float* __restrict__ adj,
    const float* __restrict__ bv0, const float* __restrict__ Wo0,
    const float* __restrict__ bo0)
{
    int bid = blockIdx.x, t = threadIdx.x;
    if (bid < PP) {
        __shared__ int snbrs[NN][8];
        __shared__ int sdeg[NN];
        if (t < NN) {
            int d = 0;
            for (int m = 0; m < NN; m++)
                if (adj[t*NN + m] > 0.f) snbrs[t][d++] = m;
            sdeg[t] = d;
        }
        __syncthreads();
        int p = bid;
        int i = p / NN, j = p % NN;
        if (t == 0) {
            int lst[8]; int cnt = 0;
            for (int s = 0; s < sdeg[i]; s++) lst[cnt++] = snbrs[i][s];
            for (int s = 0; s < sdeg[j]; s++) {
                int m = snbrs[j][s];
                bool f = false;
                for (int q = 0; q < cnt; q++) if (lst[q] == m) f = true;
                if (!f) lst[cnt++] = m;
            }
            for (int s = 0; s < 8; s++) d_mlist[p][s] = (s < cnt) ? lst[s] : lst[0];
            int nodes2[2] = {i, j};
            for (int tt = 0; tt < 2; tt++) {
                int n = nodes2[tt], dg = sdeg[n];
                d_qdeg[p][tt] = dg;
                for (int s = 0; s < 4; s++) {
                    int slot = 0;
                    if (s < dg) {
                        int m = snbrs[n][s];
                        for (int q = 0; q < cnt; q++) if (lst[q] == m) { slot = q; break; }
                    }
                    d_qslot[p][tt][s] = slot;
                }
            }
            int sl[12]; int sc2 = 0;
            sl[sc2++] = i;
            if (j != i) sl[sc2++] = j;
            for (int s = 0; s < cnt; s++) {
                int m = lst[s];
                if (m != i && m != j) sl[sc2++] = m;
            }
            d_scnt[p] = sc2;
            for (int s = 0; s < 12; s++) d_slist[p][s] = (s < sc2) ? sl[s] : sl[0];
        }
        __syncthreads();                      // d_mlist[p] visible to whole block
        if (t < BB) {
            int bp = t * PP + p;
            d_rowq[bp*2 + 0] = bp*NN + i;
            d_rowq[bp*2 + 1] = bp*NN + j;
            for (int s = 0; s < 8; s++)
                d_rowm[bp*8 + s] = bp*NN + d_mlist[p][s];
        }
        if (bid == 0 && t < NN) {
            d_deg[t] = sdeg[t];
            for (int s = 0; s < sdeg[t]; s++) d_nbrs[t][s] = snbrs[t][s];
        }
    } else {
        float acc = bo0[t];
        for (int k = 0; k < 256; k++) acc += bv0[k] * Wo0[k*256 + t];
        d_cvec[t] = acc;
    }
}

// ---------------- tf32 mma helpers ----------------
__device__ __forceinline__ unsigned f2tf(float x) {
    unsigned r; asm("cvt.rna.tf32.f32 %0, %1;" : "=r"(r) : "f"(x)); return r;
}
__device__ __forceinline__ void mma_tf32(float* c, const unsigned* a, const unsigned* b) {
    asm volatile("mma.sync.aligned.m16n8k8.row.col.f32.tf32.tf32.f32 "
        "{%0,%1,%2,%3}, {%4,%5,%6,%7}, {%8,%9}, {%0,%1,%2,%3};"
        : "+f"(c[0]), "+f"(c[1]), "+f"(c[2]), "+f"(c[3])
        : "r"(a[0]), "r"(a[1]), "r"(a[2]), "r"(a[3]), "r"(b[0]), "r"(b[1]));
}

// ---------------- wide tf32 GEMM core: 128x128 tile, K-chunk 32 ----------------
__device__ __forceinline__ void mmt_core(
    const float* __restrict__ A, int lda, const int* __restrict__ rowmap,
    const float* __restrict__ B, int ldb, const float* __restrict__ bias,
    float* __restrict__ C, int ldc, int M, int K, int row0, int col0)
{
    __shared__ unsigned As[128][36];
    __shared__ unsigned Bs[32][136];
    __shared__ int rmap[128];
    int tid = threadIdx.x;
    int lane = tid & 31, wid = tid >> 5;
    int wm = wid & 3, wn = wid >> 2;
    int gid = lane >> 2, tig = lane & 3;

    for (int r = tid; r < 128; r += 256) {
        int gi = row0 + r; if (gi > M - 1) gi = M - 1;
        rmap[r] = rowmap ? rowmap[gi] : gi;
    }
    __syncthreads();

    float acc[2][8][4];
#pragma unroll
    for (int mi = 0; mi < 2; mi++)
#pragma unroll
        for (int ni = 0; ni < 8; ni++)
#pragma unroll
            for (int q = 0; q < 4; q++) acc[mi][ni][q] = 0.f;

    int sar = tid >> 1;
    int sak = (tid & 1) * 16;
    const float* Abase = A + (size_t)rmap[sar] * lda + sak;
    int sbk = tid >> 3;
    int sbn = (tid & 7) * 16;

    for (int k0 = 0; k0 < K; k0 += 32) {
        if (k0) __syncthreads();
#pragma unroll
        for (int u = 0; u < 4; u++) {
            float4 v = *(const float4*)(Abase + k0 + u*4);
            uint4 w4; w4.x = f2tf(v.x); w4.y = f2tf(v.y); w4.z = f2tf(v.z); w4.w = f2tf(v.w);
            *(uint4*)(&As[sar][sak + u*4]) = w4;
        }
        const float* Bp = B + (size_t)(k0 + sbk) * ldb + col0 + sbn;
#pragma unroll
        for (int u = 0; u < 4; u++) {
            float4 v = *(const float4*)(Bp + u*4);
            uint4 w4; w4.x = f2tf(v.x); w4.y = f2tf(v.y); w4.z = f2tf(v.z); w4.w = f2tf(v.w);
            *(uint4*)(&Bs[sbk][sbn + u*4]) = w4;
        }
        __syncthreads();
#pragma unroll
        for (int ks = 0; ks < 4; ks++) {
            int kc0 = ks*8 + tig, kc1 = kc0 + 4;
            unsigned af[2][4], bf[8][2];
#pragma unroll
            for (int mi = 0; mi < 2; mi++) {
                int r0 = wm*32 + mi*16 + gid;
                af[mi][0] = As[r0][kc0];
                af[mi][1] = As[r0 + 8][kc0];
                af[mi][2] = As[r0][kc1];
                af[mi][3] = As[r0 + 8][kc1];
            }
#pragma unroll
            for (int ni = 0; ni < 8; ni++) {
                int n = wn*64 + ni*8 + gid;
                bf[ni][0] = Bs[kc0][n];
                bf[ni][1] = Bs[kc1][n];
            }
#pragma unroll
            for (int mi = 0; mi < 2; mi++)
#pragma unroll
                for (int ni = 0; ni < 8; ni++)
                    mma_tf32(acc[mi][ni], af[mi], bf[ni]);
        }
    }

#pragma unroll
    for (int mi = 0; mi < 2; mi++) {
#pragma unroll
        for (int half = 0; half < 2; half++) {
            int gr = row0 + wm*32 + mi*16 + gid + half*8;
            if (gr >= M) continue;
#pragma unroll
            for (int ni = 0; ni < 8; ni++) {
                int gc = col0 + wn*64 + ni*8 + tig*2;
                float v0 = acc[mi][ni][half*2 + 0];
                float v1 = acc[mi][ni][half*2 + 1];
                if (bias) { v0 += __ldg(&bias[gc]); v1 += __ldg(&bias[gc + 1]); }
                float2 o; o.x = v0; o.y = v1;
                *(float2*)&C[(size_t)gr * ldc + gc] = o;
            }
        }
    }
}

// wrappers
__global__ void __launch_bounds__(256) k_qkv(const float* __restrict__ x,
    const float* __restrict__ Wq, const float* __restrict__ Wk, const float* __restrict__ Wv) {
    const float* B = (blockIdx.z == 0) ? Wq : (blockIdx.z == 1 ? Wk : Wv);
    mmt_core(x, 256, nullptr, B, 256, nullptr, d_XQKV + blockIdx.z*256, 768,
             BPTOT, 256, blockIdx.x*128, blockIdx.y*128);
}
__global__ void __launch_bounds__(256) k_yv(const float* __restrict__ Wo0) {
    int h = blockIdx.z;
    mmt_core(d_XQKV + 512 + h*32, 768, nullptr, Wo0 + h*8192, 256, nullptr,
             d_YV + h*256, 2048, BPTOT, 32, blockIdx.x*128, blockIdx.y*128);
}
__global__ void __launch_bounds__(256) k_q2(const float* __restrict__ Wq1, const float* __restrict__ bq1) {
    mmt_core(d_E2, 256, d_rowq, Wq1, 256, bq1, d_Q2, 256,
             NQ, 256, blockIdx.x*128, blockIdx.y*128);
}
// K2/V2 gather GEMMs: z=0 -> K2 (Wk1,bk1), z=1 -> V2 (Wv1,bv1)
__global__ void __launch_bounds__(256) k_kv2(
    const float* __restrict__ Wk1, const float* __restrict__ bk1,
    const float* __restrict__ Wv1, const float* __restrict__ bv1) {
    const float* B = (blockIdx.z == 0) ? Wk1 : Wv1;
    const float* bi = (blockIdx.z == 0) ? bk1 : bv1;
    float* C = (blockIdx.z == 0) ? d_K2s : d_V2s;
    mmt_core(d_E2, 256, d_rowm, B, 256, bi, C, 256,
             BPTOT*8, 256, blockIdx.x*128, blockIdx.y*128);
}
__global__ void __launch_bounds__(256) k_z2(const float* __restrict__ Wo1, const float* __restrict__ bo1) {
    mmt_core(d_att, 256, nullptr, Wo1, 256, bo1, d_Z2, 256,
             NQ, 256, blockIdx.x*128, blockIdx.y*128);
}

// ---------------- layer-1 attention (collapsed) + E2 (slist only) + LN ----------------
__global__ void __launch_bounds__(256) k_attn1(
    const float* __restrict__ x,
    const float* __restrict__ bq0, const float* __restrict__ bk0,
    const float* __restrict__ g0, const float* __restrict__ b0)
{
    int bp = blockIdx.x;
    int p = bp % PP;
    int i = p / NN, j = p % NN;
    int tid = threadIdx.x;
    int w = tid >> 5, l = tid & 31;
    __shared__ float sA[8], sBq[8], sBk[8], sC[8];
    __shared__ float sc[NN][8];
    __shared__ float red1[8], red2[8];

    {
        int idx = w * 32 + l;
        float xq = d_XQKV[(size_t)bp*768 + idx];
        float xk = d_XQKV[(size_t)bp*768 + 256 + idx];
        float bqv = bq0[idx], bkv = bk0[idx];
        float a = xq * xk, bqd = xq * bkv, bkd = bqv * xk, c = bqv * bkv;
#pragma unroll
        for (int o = 16; o > 0; o >>= 1) {
            a   += __shfl_xor_sync(~0u, a, o);
            bqd += __shfl_xor_sync(~0u, bqd, o);
            bkd += __shfl_xor_sync(~0u, bkd, o);
            c   += __shfl_xor_sync(~0u, c, o);
        }
        if (l == 0) { sA[w] = a; sBq[w] = bqd; sBk[w] = bkd; sC[w] = c; }
    }
    __syncthreads();

    if (tid < NN * 8) {
        int n = tid >> 3, h = tid & 7;
        float A = sA[h], Bq = sBq[h], Bk = sBk[h], C = sC[h];
        float an = (float)((n == i) + (n == j));
        int dg = d_deg[n];
        float scm[4], amv[4];
        float mx = -1e30f;
        for (int s = 0; s < dg; s++) {
            int m = d_nbrs[n][s];
            float am = (float)((m == i) + (m == j));
            float sv = INV_SQRT_HD * (an*am*A + an*Bq + am*Bk + C);
            scm[s] = sv; amv[s] = am;
            mx = fmaxf(mx, sv);
        }
        float den = 0.f, num = 0.f;
        for (int s = 0; s < dg; s++) {
            float e = __expf(scm[s] - mx);
            den += e; num += e * amv[s];
        }
        sc[n][h] = num / den;
    }
    __syncthreads();

    int d = tid;
    float xd = x[(size_t)bp*256 + d];
    float cv = d_cvec[d];
    float yv[8];
#pragma unroll
    for (int h = 0; h < 8; h++) yv[h] = d_YV[(size_t)bp*2048 + h*256 + d];
    float gd = g0[d], bd = b0[d];
    int scn = d_scnt[p];
    for (int si = 0; si < scn; si++) {
        int n = d_slist[p][si];
        float an = (float)((n == i) + (n == j));
        float v = cv + an * xd;
#pragma unroll
        for (int h = 0; h < 8; h++) v += sc[n][h] * yv[h];
        float s1 = v, s2 = v * v;
#pragma unroll
        for (int o = 16; o > 0; o >>= 1) {
            s1 += __shfl_xor_sync(~0u, s1, o);
            s2 += __shfl_xor_sync(~0u, s2, o);
        }
        __syncthreads();
        if (l == 0) { red1[w] = s1; red2[w] = s2; }
        __syncthreads();
        float mu = 0.f, m2 = 0.f;
#pragma unroll
        for (int q = 0; q < 8; q++) { mu += red1[q]; m2 += red2[q]; }
        mu *= (1.f/256.f); m2 *= (1.f/256.f);
        float rs = rsqrtf(m2 - mu*mu + LN_EPS);
        d_E2[((size_t)bp*NN + n)*256 + d] = (v - mu) * rs * gd + bd;
    }
}

// ---------------- layer-2 attention (sparse: 2 queries, <=4 keys each) ----------------
__global__ void __launch_bounds__(256) k_attn2() {
    int bp = blockIdx.x;
    int p = bp % PP;
    int tid = threadIdx.x;
    int w = tid >> 5, l = tid & 31;
    __shared__ float ssw[2][8][4];

    for (int task = w; task < 16; task += 8) {
        int t = task & 1, h = task >> 1;
        int dg = d_qdeg[p][t];
        float q = d_Q2[((size_t)bp*2 + t)*256 + h*32 + l];
        float scs[4];
        for (int s = 0; s < dg; s++) {
            int slot = d_qslot[p][t][s];
            float k = d_K2s[((size_t)bp*8 + slot)*256 + h*32 + l];
            float dt = q * k;
#pragma unroll
            for (int o = 16; o > 0; o >>= 1) dt += __shfl_xor_sync(~0u, dt, o);
            scs[s] = dt * INV_SQRT_HD;
        }
        if (l == 0) {
            float mx = -1e30f;
            for (int s = 0; s < dg; s++) mx = fmaxf(mx, scs[s]);
            float e[4]; float den = 0.f;
            for (int s = 0; s < dg; s++) { e[s] = __expf(scs[s] - mx); den += e[s]; }
            for (int s = 0; s < 4; s++) ssw[t][h][s] = (s < dg) ? e[s] / den : 0.f;
        }
    }
    __syncthreads();

    int d = tid, h = d >> 5;
#pragma unroll
    for (int t = 0; t < 2; t++) {
        int dg = d_qdeg[p][t];
        float acc = 0.f;
        for (int s = 0; s < dg; s++) {
            int slot = d_qslot[p][t][s];
            acc += ssw[t][h][s] * d_V2s[((size_t)bp*8 + slot)*256 + d];
        }
        d_att[((size_t)bp*2 + t)*256 + d] = acc;
    }
}

// ---------------- final LN + readout (single barrier pair) ----------------
__global__ void __launch_bounds__(256) k_final(
    const float* __restrict__ x,
    const float* __restrict__ g1, const float* __restrict__ b1,
    float* __restrict__ out)
{
    int bp = blockIdx.x;
    int p = bp % PP;
    int i = p / NN, jn = p % NN;
    int tid = threadIdx.x, w = tid >> 5, l = tid & 31;
    __shared__ float red[8][4];
    int d = tid;
    float gd = g1[d], bd = b1[d];
    float vA = d_Z2[((size_t)bp*2 + 0)*256 + d] + d_E2[((size_t)bp*NN + i)*256 + d];
    float vB = d_Z2[((size_t)bp*2 + 1)*256 + d] + d_E2[((size_t)bp*NN + jn)*256 + d];
    float s1a = vA, s2a = vA*vA, s1b = vB, s2b = vB*vB;
#pragma unroll
    for (int o = 16; o > 0; o >>= 1) {
        s1a += __shfl_xor_sync(~0u, s1a, o);
        s2a += __shfl_xor_sync(~0u, s2a, o);
        s1b += __shfl_xor_sync(~0u, s1b, o);
        s2b += __shfl_xor_sync(~0u, s2b, o);
    }
    if (l == 0) { red[w][0] = s1a; red[w][1] = s2a; red[w][2] = s1b; red[w][3] = s2b; }
    __syncthreads();
    float t1a = 0.f, t2a = 0.f, t1b = 0.f, t2b = 0.f;
#pragma unroll
    for (int q = 0; q < 8; q++) {
        t1a += red[q][0]; t2a += red[q][1];
        t1b += red[q][2]; t2b += red[q][3];
    }
    float muA = t1a*(1.f/256.f), mA = t2a*(1.f/256.f);
    float muB = t1b*(1.f/256.f), mB = t2b*(1.f/256.f);
    float rsA = rsqrtf(mA - muA*muA + LN_EPS);
    float rsB = rsqrtf(mB - muB*muB + LN_EPS);
    float e3a = (vA - muA) * rsA * gd + bd;
    float e3b = (vB - muB) * rsB * gd + bd;
    out[(size_t)bp*256 + d] = 0.5f * (e3a + e3b) + x[(size_t)bp*256 + d];
}

// ---------------- launch ----------------
extern "C" void kernel_launch(void* const* d_in, const int* in_sizes, int n_in,
                              void* d_out, int out_size)
{
    const float* x   = (const float*)d_in[0];
    const float* adj = (const float*)d_in[1];
    const float* Wq  = (const float*)d_in[2];
    const float* bq  = (const float*)d_in[3];
    const float* Wk  = (const float*)d_in[4];
    const float* bk  = (const float*)d_in[5];
    const float* Wv  = (const float*)d_in[6];
    const float* bv  = (const float*)d_in[7];
    const float* Wo  = (const float*)d_in[8];
    const float* bo  = (const float*)d_in[9];
    const float* lg  = (const float*)d_in[10];
    const float* lb  = (const float*)d_in[11];
    float* out = (float*)d_out;

    k_setup<<<PP + 1, 256>>>(adj, bv, Wo, bo);

    k_qkv<<<dim3(46, 2, 3), 256>>>(x, Wq, Wk, Wv);
    k_yv<<<dim3(46, 2, 8), 256>>>(Wo);

    k_attn1<<<BPTOT, 256>>>(x, bq, bk, lg, lb);

    k_q2<<<dim3(91, 2), 256>>>(Wq + 65536, bq + 256);
    k_kv2<<<dim3(361, 2, 2), 256>>>(Wk + 65536, bk + 256, Wv + 65536, bv + 256);

    k_attn2<<<BPTOT, 256>>>();

    k_z2<<<dim3(91, 2), 256>>>(Wo + 65536, bo + 256);

    k_final<<<BPTOT, 256>>>(x, lg + 256, lb + 256, out);
}

// round 9
// speedup vs baseline: 1.2661x; 1.2661x over previous
#include <cuda_runtime.h>

#define NN 19
#define PP 361
#define BB 16
#define HH 8
#define BPTOT (BB*PP)            // 5776
#define NQ (BPTOT*2)             // 11552
#define LN_EPS 1e-5f
#define INV_SQRT_HD 0.1767766952966369f   // 1/sqrt(32)

// ---------------- scratch: device globals ----------------
__device__ float d_XQKV[BPTOT*768];                   // [bp][xq|xk|xv]
__device__ float d_YV[(size_t)BPTOT*2048];            // [bp][h][256]
__device__ float d_E2[(size_t)BPTOT*NN*256];          // [bp][n][256] (slist rows valid)
__device__ float d_Q2[(size_t)NQ*256];
__device__ float d_U[(size_t)NQ*2048];                // [row][h][256] = Wk_h^T q_h
__device__ float d_Zz[(size_t)NQ*2048];               // [row][h][256] = sum_m w*E2_m
__device__ float d_att[(size_t)NQ*256];
__device__ float d_Z2[(size_t)NQ*256];
__device__ float d_WkT[65536];
__device__ float d_cvec[256];
__device__ int d_deg[NN];
__device__ int d_nbrs[NN][8];
__device__ int d_mlist[PP][8];
__device__ int d_qdeg[PP][2];
__device__ int d_qslot[PP][2][4];
__device__ int d_scnt[PP];
__device__ int d_slist[PP][12];
__device__ int d_rowq[NQ];

// ---------------- fused setup ----------------
__global__ void __launch_bounds__(256) k_setup(
    const float* __restrict__ adj, const float* __restrict__ Wk1,
    const float* __restrict__ bv0, const float* __restrict__ Wo0,
    const float* __restrict__ bo0)
{
    int bid = blockIdx.x, t = threadIdx.x;
    if (bid < PP) {
        __shared__ int snbrs[NN][8];
        __shared__ int sdeg[NN];
        if (t < NN) {
            int d = 0;
            for (int m = 0; m < NN; m++)
                if (adj[t*NN + m] > 0.f) snbrs[t][d++] = m;
            sdeg[t] = d;
        }
        __syncthreads();
        int p = bid;
        int i = p / NN, j = p % NN;
        if (t == 0) {
            int lst[8]; int cnt = 0;
            for (int s = 0; s < sdeg[i]; s++) lst[cnt++] = snbrs[i][s];
            for (int s = 0; s < sdeg[j]; s++) {
                int m = snbrs[j][s];
                bool f = false;
                for (int q = 0; q < cnt; q++) if (lst[q] == m) f = true;
                if (!f) lst[cnt++] = m;
            }
            for (int s = 0; s < 8; s++) d_mlist[p][s] = (s < cnt) ? lst[s] : lst[0];
            int nodes2[2] = {i, j};
            for (int tt = 0; tt < 2; tt++) {
                int n = nodes2[tt], dg = sdeg[n];
                d_qdeg[p][tt] = dg;
                for (int s = 0; s < 4; s++) {
                    int slot = 0;
                    if (s < dg) {
                        int m = snbrs[n][s];
                        for (int q = 0; q < cnt; q++) if (lst[q] == m) { slot = q; break; }
                    }
                    d_qslot[p][tt][s] = slot;
                }
            }
            int sl[12]; int sc2 = 0;
            sl[sc2++] = i;
            if (j != i) sl[sc2++] = j;
            for (int s = 0; s < cnt; s++) {
                int m = lst[s];
                if (m != i && m != j) sl[sc2++] = m;
            }
            d_scnt[p] = sc2;
            for (int s = 0; s < 12; s++) d_slist[p][s] = (s < sc2) ? sl[s] : sl[0];
        }
        if (t < BB) {
            int bp = t * PP + p;
            d_rowq[bp*2 + 0] = bp*NN + i;
            d_rowq[bp*2 + 1] = bp*NN + j;
        }
        if (bid == 0 && t < NN) {
            d_deg[t] = sdeg[t];
            for (int s = 0; s < sdeg[t]; s++) d_nbrs[t][s] = snbrs[t][s];
        }
    } else if (bid < PP + 16) {
        int e0 = (bid - PP) * 16;
        for (int e = e0; e < e0 + 16; e++)
            d_WkT[e*256 + t] = Wk1[t*256 + e];
    } else {
        float acc = bo0[t];
        for (int k = 0; k < 256; k++) acc += bv0[k] * Wo0[k*256 + t];
        d_cvec[t] = acc;
    }
}

// ---------------- mma / cp.async helpers ----------------
__device__ __forceinline__ void mma_tf32(float* c, const unsigned* a, const unsigned* b) {
    asm volatile("mma.sync.aligned.m16n8k8.row.col.f32.tf32.tf32.f32 "
        "{%0,%1,%2,%3}, {%4,%5,%6,%7}, {%8,%9}, {%0,%1,%2,%3};"
        : "+f"(c[0]), "+f"(c[1]), "+f"(c[2]), "+f"(c[3])
        : "r"(a[0]), "r"(a[1]), "r"(a[2]), "r"(a[3]), "r"(b[0]), "r"(b[1]));
}
__device__ __forceinline__ void cp16(unsigned s, const float* g) {
    asm volatile("cp.async.cg.shared.global [%0], [%1], 16;" :: "r"(s), "l"(g));
}
__device__ __forceinline__ void cp_commit() {
    asm volatile("cp.async.commit_group;");
}
template<int N> __device__ __forceinline__ void cp_wait() {
    asm volatile("cp.async.wait_group %0;" :: "n"(N));
}

// ---------------- wide tf32 GEMM core: 128x128 tile, K-chunk 16, double-buffered ----------------
__device__ __forceinline__ void mmt_core(
    const float* __restrict__ A, int lda, const int* __restrict__ rowmap,
    const float* __restrict__ B, int ldb, const float* __restrict__ bias,
    float* __restrict__ C, int ldc, int M, int K, int row0, int col0)
{
    __shared__ __align__(16) unsigned As[2][128][20];   // [buf][m][k], raw fp32 bits
    __shared__ __align__(16) unsigned Bs[2][16][136];   // [buf][k][n]
    __shared__ int rmap[128];
    int tid = threadIdx.x;
    int lane = tid & 31, wid = tid >> 5;
    int wm = wid & 3, wn = wid >> 2;          // 4 x 2 warp grid
    int gid = lane >> 2, tig = lane & 3;

    for (int r = tid; r < 128; r += 256) {
        int gi = row0 + r; if (gi > M - 1) gi = M - 1;
        rmap[r] = rowmap ? rowmap[gi] : gi;
    }
    __syncthreads();

    float acc[2][8][4];
#pragma unroll
    for (int mi = 0; mi < 2; mi++)
#pragma unroll
        for (int ni = 0; ni < 8; ni++)
#pragma unroll
            for (int q = 0; q < 4; q++) acc[mi][ni][q] = 0.f;

    int sar = tid >> 1, sak = (tid & 1) * 8;     // A: 128 rows x 16 k, 8 floats/thread
    const float* Abase = A + (size_t)rmap[sar] * lda + sak;
    int sbk = tid >> 4, sbn = (tid & 15) * 8;    // B: 16 k-rows x 128 cols, 8 floats/thread
    const float* Bbase = B + (size_t)sbk * ldb + col0 + sbn;

    unsigned aAddr[2], bAddr[2];
#pragma unroll
    for (int b = 0; b < 2; b++) {
        aAddr[b] = (unsigned)__cvta_generic_to_shared(&As[b][sar][sak]);
        bAddr[b] = (unsigned)__cvta_generic_to_shared(&Bs[b][sbk][sbn]);
    }

    int nc = K >> 4;
    // prologue: stage chunk 0 -> buf 0
    cp16(aAddr[0], Abase);       cp16(aAddr[0] + 16, Abase + 4);
    cp16(bAddr[0], Bbase);       cp16(bAddr[0] + 16, Bbase + 4);
    cp_commit();

    for (int c = 0; c < nc; c++) {
        int cur = c & 1;
        if (c + 1 < nc) {
            int nxt = cur ^ 1;
            const float* ga = Abase + (c + 1) * 16;
            const float* gb = Bbase + (size_t)(c + 1) * 16 * ldb;
            cp16(aAddr[nxt], ga);       cp16(aAddr[nxt] + 16, ga + 4);
            cp16(bAddr[nxt], gb);       cp16(bAddr[nxt] + 16, gb + 4);
            cp_commit();
            cp_wait<1>();
        } else {
            cp_wait<0>();
        }
        __syncthreads();
#pragma unroll
        for (int ks = 0; ks < 2; ks++) {
            int kc0 = ks*8 + tig, kc1 = kc0 + 4;
            unsigned af[2][4], bf[8][2];
#pragma unroll
            for (int mi = 0; mi < 2; mi++) {
                int r0 = wm*32 + mi*16 + gid;
                af[mi][0] = As[cur][r0][kc0];
                af[mi][1] = As[cur][r0 + 8][kc0];
                af[mi][2] = As[cur][r0][kc1];
                af[mi][3] = As[cur][r0 + 8][kc1];
            }
#pragma unroll
            for (int ni = 0; ni < 8; ni++) {
                int n = wn*64 + ni*8 + gid;
                bf[ni][0] = Bs[cur][kc0][n];
                bf[ni][1] = Bs[cur][kc1][n];
            }
#pragma unroll
            for (int mi = 0; mi < 2; mi++)
#pragma unroll
                for (int ni = 0; ni < 8; ni++)
                    mma_tf32(acc[mi][ni], af[mi], bf[ni]);
        }
        __syncthreads();
    }

#pragma unroll
    for (int mi = 0; mi < 2; mi++) {
#pragma unroll
        for (int half = 0; half < 2; half++) {
            int gr = row0 + wm*32 + mi*16 + gid + half*8;
            if (gr >= M) continue;
#pragma unroll
            for (int ni = 0; ni < 8; ni++) {
                int gc = col0 + wn*64 + ni*8 + tig*2;
                float v0 = acc[mi][ni][half*2 + 0];
                float v1 = acc[mi][ni][half*2 + 1];
                if (bias) { v0 += __ldg(&bias[gc]); v1 += __ldg(&bias[gc + 1]); }
                float2 o; o.x = v0; o.y = v1;
                *(float2*)&C[(size_t)gr * ldc + gc] = o;
            }
        }
    }
}

// wrappers
__global__ void __launch_bounds__(256) k_qkv(const float* __restrict__ x,
    const float* __restrict__ Wq, const float* __restrict__ Wk, const float* __restrict__ Wv) {
    const float* B = (blockIdx.z == 0) ? Wq : (blockIdx.z == 1 ? Wk : Wv);
    mmt_core(x, 256, nullptr, B, 256, nullptr, d_XQKV + blockIdx.z*256, 768,
             BPTOT, 256, blockIdx.x*128, blockIdx.y*128);
}
__global__ void __launch_bounds__(256) k_yv(const float* __restrict__ Wo0) {
    int h = blockIdx.z;
    mmt_core(d_XQKV + 512 + h*32, 768, nullptr, Wo0 + h*8192, 256, nullptr,
             d_YV + h*256, 2048, BPTOT, 32, blockIdx.x*128, blockIdx.y*128);
}
__global__ void __launch_bounds__(256) k_q2(const float* __restrict__ Wq1, const float* __restrict__ bq1) {
    mmt_core(d_E2, 256, d_rowq, Wq1, 256, bq1, d_Q2, 256,
             NQ, 256, blockIdx.x*128, blockIdx.y*128);
}
__global__ void __launch_bounds__(256) k_u() {
    int h = blockIdx.z;
    mmt_core(d_Q2 + h*32, 256, nullptr, d_WkT + h*32*256, 256, nullptr,
             d_U + h*256, 2048, NQ, 32, blockIdx.x*128, blockIdx.y*128);
}
__global__ void __launch_bounds__(256) k_z2(const float* __restrict__ Wo1, const float* __restrict__ bo1) {
    mmt_core(d_att, 256, nullptr, Wo1, 256, bo1, d_Z2, 256,
             NQ, 256, blockIdx.x*128, blockIdx.y*128);
}

// ---------------- narrow tf32 GEMM (N=32), double-buffered: att_h = Zz_h @ Wv_h + bv_h ----------------
__global__ void __launch_bounds__(256) k_att(const float* __restrict__ Wv1,
                                             const float* __restrict__ bv1) {
    __shared__ __align__(16) unsigned As[2][128][20];
    __shared__ __align__(16) unsigned Bs[2][16][40];
    int h = blockIdx.y;
    int row0 = blockIdx.x * 128;
    const float* A = d_Zz + h*256;       // lda 2048
    const float* B = Wv1 + h*32;         // ldb 256
    int tid = threadIdx.x, lane = tid & 31, wid = tid >> 5;
    int gid = lane >> 2, tig = lane & 3;

    float acc[4][4];
#pragma unroll
    for (int ni = 0; ni < 4; ni++)
#pragma unroll
        for (int q = 0; q < 4; q++) acc[ni][q] = 0.f;

    int sar = tid >> 1, sak = (tid & 1) * 8;
    int arow = row0 + sar; if (arow > NQ - 1) arow = NQ - 1;
    const float* Abase = A + (size_t)arow * 2048 + sak;
    // B: 16 k-rows x 32 cols = 512 floats; threads 0..127 stage one float4 each
    int sbk = tid >> 3, sbc = (tid & 7) * 4;
    const float* Bbase = B + (size_t)sbk * 256 + sbc;

    unsigned aAddr[2], bAddr[2];
#pragma unroll
    for (int b = 0; b < 2; b++) {
        aAddr[b] = (unsigned)__cvta_generic_to_shared(&As[b][sar][sak]);
        bAddr[b] = (unsigned)__cvta_generic_to_shared(&Bs[b][sbk][sbc]);
    }
    bool bstage = (tid < 128);

    cp16(aAddr[0], Abase);       cp16(aAddr[0] + 16, Abase + 4);
    if (bstage) cp16(bAddr[0], Bbase);
    cp_commit();

    for (int c = 0; c < 16; c++) {
        int cur = c & 1;
        if (c + 1 < 16) {
            int nxt = cur ^ 1;
            const float* ga = Abase + (c + 1) * 16;
            cp16(aAddr[nxt], ga);       cp16(aAddr[nxt] + 16, ga + 4);
            if (bstage) cp16(bAddr[nxt], Bbase + (size_t)(c + 1) * 16 * 256);
            cp_commit();
            cp_wait<1>();
        } else {
            cp_wait<0>();
        }
        __syncthreads();
#pragma unroll
        for (int ks = 0; ks < 2; ks++) {
            int kc0 = ks*8 + tig, kc1 = kc0 + 4;
            int r0 = wid*16 + gid;
            unsigned af[4];
            af[0] = As[cur][r0][kc0]; af[1] = As[cur][r0 + 8][kc0];
            af[2] = As[cur][r0][kc1]; af[3] = As[cur][r0 + 8][kc1];
#pragma unroll
            for (int ni = 0; ni < 4; ni++) {
                unsigned bf[2];
                bf[0] = Bs[cur][kc0][ni*8 + gid];
                bf[1] = Bs[cur][kc1][ni*8 + gid];
                mma_tf32(acc[ni], af, bf);
            }
        }
        __syncthreads();
    }
#pragma unroll
    for (int half = 0; half < 2; half++) {
        int gr = row0 + wid*16 + gid + half*8;
        if (gr >= NQ) continue;
#pragma unroll
        for (int ni = 0; ni < 4; ni++) {
            int gc = ni*8 + tig*2;
            float v0 = acc[ni][half*2 + 0] + __ldg(&bv1[h*32 + gc]);
            float v1 = acc[ni][half*2 + 1] + __ldg(&bv1[h*32 + gc + 1]);
            float2 o; o.x = v0; o.y = v1;
            *(float2*)&d_att[(size_t)gr*256 + h*32 + gc] = o;
        }
    }
}

// ---------------- layer-1 attention (collapsed) + E2 (slist only) + LN — round-5 exact ----------------
__global__ void __launch_bounds__(256) k_attn1(
    const float* __restrict__ x,
    const float* __restrict__ bq0, const float* __restrict__ bk0,
    const float* __restrict__ g0, const float* __restrict__ b0)
{
    int bp = blockIdx.x;
    int p = bp % PP;
    int i = p / NN, j = p % NN;
    int tid = threadIdx.x;
    int w = tid >> 5, l = tid & 31;
    __shared__ float sA[8], sBq[8], sBk[8], sC[8];
    __shared__ float sc[NN][8];
    __shared__ float red1[8], red2[8];

    {
        int idx = w * 32 + l;
        float xq = d_XQKV[(size_t)bp*768 + idx];
        float xk = d_XQKV[(size_t)bp*768 + 256 + idx];
        float bqv = bq0[idx], bkv = bk0[idx];
        float a = xq * xk, bqd = xq * bkv, bkd = bqv * xk, c = bqv * bkv;
#pragma unroll
        for (int o = 16; o > 0; o >>= 1) {
            a   += __shfl_xor_sync(~0u, a, o);
            bqd += __shfl_xor_sync(~0u, bqd, o);
            bkd += __shfl_xor_sync(~0u, bkd, o);
            c   += __shfl_xor_sync(~0u, c, o);
        }
        if (l == 0) { sA[w] = a; sBq[w] = bqd; sBk[w] = bkd; sC[w] = c; }
    }
    __syncthreads();

    if (tid < NN * 8) {
        int n = tid >> 3, h = tid & 7;
        float A = sA[h], Bq = sBq[h], Bk = sBk[h], C = sC[h];
        float an = (float)((n == i) + (n == j));
        int dg = d_deg[n];
        float scm[4], amv[4];
        float mx = -1e30f;
        for (int s = 0; s < dg; s++) {
            int m = d_nbrs[n][s];
            float am = (float)((m == i) + (m == j));
            float sv = INV_SQRT_HD * (an*am*A + an*Bq + am*Bk + C);
            scm[s] = sv; amv[s] = am;
            mx = fmaxf(mx, sv);
        }
        float den = 0.f, num = 0.f;
        for (int s = 0; s < dg; s++) {
            float e = __expf(scm[s] - mx);
            den += e; num += e * amv[s];
        }
        sc[n][h] = num / den;
    }
    __syncthreads();

    int d = tid;
    float xd = x[(size_t)bp*256 + d];
    float cv = d_cvec[d];
    float yv[8];
#pragma unroll
    for (int h = 0; h < 8; h++) yv[h] = d_YV[(size_t)bp*2048 + h*256 + d];
    float gd = g0[d], bd = b0[d];
    int scn = d_scnt[p];
    for (int si = 0; si < scn; si++) {
        int n = d_slist[p][si];
        float an = (float)((n == i) + (n == j));
        float v = cv + an * xd;
#pragma unroll
        for (int h = 0; h < 8; h++) v += sc[n][h] * yv[h];
        float s1 = v, s2 = v * v;
#pragma unroll
        for (int o = 16; o > 0; o >>= 1) {
            s1 += __shfl_xor_sync(~0u, s1, o);
            s2 += __shfl_xor_sync(~0u, s2, o);
        }
        __syncthreads();
        if (l == 0) { red1[w] = s1; red2[w] = s2; }
        __syncthreads();
        float mu = 0.f, m2 = 0.f;
#pragma unroll
        for (int q = 0; q < 8; q++) { mu += red1[q]; m2 += red2[q]; }
        mu *= (1.f/256.f); m2 *= (1.f/256.f);
        float rs = rsqrtf(m2 - mu*mu + LN_EPS);
        d_E2[((size_t)bp*NN + n)*256 + d] = (v - mu) * rs * gd + bd;
    }
}

// ---------------- layer-2: scores via U, softmax, z = sum_m w*E2_m ----------------
__global__ void __launch_bounds__(256) k_score_z(const float* __restrict__ bk1) {
    int bp = blockIdx.x;
    int p = bp % PP;
    int tid = threadIdx.x;
    int w = tid >> 5, l = tid & 31;
    __shared__ __align__(16) float sEm[8][256];
    __shared__ float sw[2][8][4];

    {
        int m = d_mlist[p][w];
        const float4* src = (const float4*)(d_E2 + ((size_t)bp*NN + m)*256);
        float4* dst = (float4*)sEm[w];
        dst[l] = src[l];
        dst[l + 32] = src[l + 32];
    }
    __syncthreads();

    for (int task = w; task < 16; task += 8) {
        int t = task & 1, h = task >> 1;
        int row = bp*2 + t;
        float qv = d_Q2[(size_t)row*256 + h*32 + l];
        float qb = qv * bk1[h*32 + l];
#pragma unroll
        for (int o = 16; o > 0; o >>= 1) qb += __shfl_xor_sync(~0u, qb, o);
        float u[8];
        const float* Up = d_U + (size_t)row*2048 + h*256;
#pragma unroll
        for (int q = 0; q < 8; q++) u[q] = Up[q*32 + l];
        int dg = d_qdeg[p][t];
        float scs[4];
        for (int s = 0; s < dg; s++) {
            int slot = d_qslot[p][t][s];
            float dt = 0.f;
#pragma unroll
            for (int q = 0; q < 8; q++) dt += u[q] * sEm[slot][q*32 + l];
#pragma unroll
            for (int o = 16; o > 0; o >>= 1) dt += __shfl_xor_sync(~0u, dt, o);
            scs[s] = (dt + qb) * INV_SQRT_HD;
        }
        if (l == 0) {
            float mx = -1e30f;
            for (int s = 0; s < dg; s++) mx = fmaxf(mx, scs[s]);
            float e[4]; float den = 0.f;
            for (int s = 0; s < dg; s++) { e[s] = __expf(scs[s] - mx); den += e[s]; }
            for (int s = 0; s < 4; s++) sw[t][h][s] = (s < dg) ? e[s] / den : 0.f;
        }
    }
    __syncthreads();

    int d = tid;
#pragma unroll
    for (int t = 0; t < 2; t++) {
        int dg = d_qdeg[p][t];
        int sl[4]; float em[4];
#pragma unroll
        for (int s = 0; s < 4; s++) {
            sl[s] = d_qslot[p][t][s];
            em[s] = sEm[sl[s]][d];
        }
#pragma unroll
        for (int h = 0; h < 8; h++) {
            float acc = 0.f;
            for (int s = 0; s < dg; s++) acc += sw[t][h][s] * em[s];
            d_Zz[((size_t)(bp*2 + t)*8 + h)*256 + d] = acc;
        }
    }
}

// ---------------- final LN + readout (single barrier pair) ----------------
__global__ void __launch_bounds__(256) k_final(
    const float* __restrict__ x,
    const float* __restrict__ g1, const float* __restrict__ b1,
    float* __restrict__ out)
{
    int bp = blockIdx.x;
    int p = bp % PP;
    int i = p / NN, jn = p % NN;
    int tid = threadIdx.x, w = tid >> 5, l = tid & 31;
    __shared__ float red[8][4];
    int d = tid;
    float gd = g1[d], bd = b1[d];
    float vA = d_Z2[((size_t)bp*2 + 0)*256 + d] + d_E2[((size_t)bp*NN + i)*256 + d];
    float vB = d_Z2[((size_t)bp*2 + 1)*256 + d] + d_E2[((size_t)bp*NN + jn)*256 + d];
    float s1a = vA, s2a = vA*vA, s1b = vB, s2b = vB*vB;
#pragma unroll
    for (int o = 16; o > 0; o >>= 1) {
        s1a += __shfl_xor_sync(~0u, s1a, o);
        s2a += __shfl_xor_sync(~0u, s2a, o);
        s1b += __shfl_xor_sync(~0u, s1b, o);
        s2b += __shfl_xor_sync(~0u, s2b, o);
    }
    if (l == 0) { red[w][0] = s1a; red[w][1] = s2a; red[w][2] = s1b; red[w][3] = s2b; }
    __syncthreads();
    float t1a = 0.f, t2a = 0.f, t1b = 0.f, t2b = 0.f;
#pragma unroll
    for (int q = 0; q < 8; q++) {
        t1a += red[q][0]; t2a += red[q][1];
        t1b += red[q][2]; t2b += red[q][3];
    }
    float muA = t1a*(1.f/256.f), mA = t2a*(1.f/256.f);
    float muB = t1b*(1.f/256.f), mB = t2b*(1.f/256.f);
    float rsA = rsqrtf(mA - muA*muA + LN_EPS);
    float rsB = rsqrtf(mB - muB*muB + LN_EPS);
    float e3a = (vA - muA) * rsA * gd + bd;
    float e3b = (vB - muB) * rsB * gd + bd;
    out[(size_t)bp*256 + d] = 0.5f * (e3a + e3b) + x[(size_t)bp*256 + d];
}

// ---------------- launch ----------------
extern "C" void kernel_launch(void* const* d_in, const int* in_sizes, int n_in,
                              void* d_out, int out_size)
{
    const float* x   = (const float*)d_in[0];
    const float* adj = (const float*)d_in[1];
    const float* Wq  = (const float*)d_in[2];
    const float* bq  = (const float*)d_in[3];
    const float* Wk  = (const float*)d_in[4];
    const float* bk  = (const float*)d_in[5];
    const float* Wv  = (const float*)d_in[6];
    const float* bv  = (const float*)d_in[7];
    const float* Wo  = (const float*)d_in[8];
    const float* bo  = (const float*)d_in[9];
    const float* lg  = (const float*)d_in[10];
    const float* lb  = (const float*)d_in[11];
    float* out = (float*)d_out;

    k_setup<<<PP + 17, 256>>>(adj, Wk + 65536, bv, Wo, bo);

    k_qkv<<<dim3(46, 2, 3), 256>>>(x, Wq, Wk, Wv);
    k_yv<<<dim3(46, 2, 8), 256>>>(Wo);

    k_attn1<<<BPTOT, 256>>>(x, bq, bk, lg, lb);

    k_q2<<<dim3(91, 2), 256>>>(Wq + 65536, bq + 256);
    k_u<<<dim3(91, 2, 8), 256>>>();

    k_score_z<<<BPTOT, 256>>>(bk + 256);

    k_att<<<dim3(91, 8), 256>>>(Wv + 65536, bv + 256);
    k_z2<<<dim3(91, 2), 256>>>(Wo + 65536, bo + 256);

    k_final<<<BPTOT, 256>>>(x, lg + 256, lb + 256, out);
}

// round 10
// speedup vs baseline: 1.3014x; 1.0278x over previous
#include <cuda_runtime.h>

#define NN 19
#define PP 361
#define BB 16
#define HH 8
#define BPTOT (BB*PP)            // 5776
#define NQ (BPTOT*2)             // 11552
#define LN_EPS 1e-5f
#define INV_SQRT_HD 0.1767766952966369f   // 1/sqrt(32)

// ---------------- scratch: device globals ----------------
__device__ float d_XQKV[BPTOT*768];                   // [bp][xq|xk|xv]
__device__ float d_YV[(size_t)BPTOT*2048];            // [bp][h][256]
__device__ float d_E2[(size_t)BPTOT*NN*256];          // [bp][n][256] (slist rows valid)
__device__ float d_Q2[(size_t)NQ*256];
__device__ float d_U[(size_t)NQ*2048];                // [row][h][256] = Wk_h^T q_h
__device__ float d_Zz[(size_t)NQ*2048];               // [row][h][256] = sum_m w*E2_m
__device__ float d_att[(size_t)NQ*256];
__device__ float d_Z2[(size_t)NQ*256];
__device__ float d_WkT[65536];
__device__ float d_cvec[256];
__device__ int d_deg[NN];
__device__ int d_nbrs[NN][8];
__device__ int d_mlist[PP][8];
__device__ int d_qdeg[PP][2];
__device__ int d_qslot[PP][2][4];
__device__ int d_scnt[PP];
__device__ int d_slist[PP][12];
__device__ int d_rowq[NQ];

// ---------------- fused setup ----------------
__global__ void __launch_bounds__(256) k_setup(
    const float* __restrict__ adj, const float* __restrict__ Wk1,
    const float* __restrict__ bv0, const float* __restrict__ Wo0,
    const float* __restrict__ bo0)
{
    int bid = blockIdx.x, t = threadIdx.x;
    if (bid < PP) {
        __shared__ int snbrs[NN][8];
        __shared__ int sdeg[NN];
        if (t < NN) {
            int d = 0;
            for (int m = 0; m < NN; m++)
                if (adj[t*NN + m] > 0.f) snbrs[t][d++] = m;
            sdeg[t] = d;
        }
        __syncthreads();
        int p = bid;
        int i = p / NN, j = p % NN;
        if (t == 0) {
            int lst[8]; int cnt = 0;
            for (int s = 0; s < sdeg[i]; s++) lst[cnt++] = snbrs[i][s];
            for (int s = 0; s < sdeg[j]; s++) {
                int m = snbrs[j][s];
                bool f = false;
                for (int q = 0; q < cnt; q++) if (lst[q] == m) f = true;
                if (!f) lst[cnt++] = m;
            }
            for (int s = 0; s < 8; s++) d_mlist[p][s] = (s < cnt) ? lst[s] : lst[0];
            int nodes2[2] = {i, j};
            for (int tt = 0; tt < 2; tt++) {
                int n = nodes2[tt], dg = sdeg[n];
                d_qdeg[p][tt] = dg;
                for (int s = 0; s < 4; s++) {
                    int slot = 0;
                    if (s < dg) {
                        int m = snbrs[n][s];
                        for (int q = 0; q < cnt; q++) if (lst[q] == m) { slot = q; break; }
                    }
                    d_qslot[p][tt][s] = slot;
                }
            }
            int sl[12]; int sc2 = 0;
            sl[sc2++] = i;
            if (j != i) sl[sc2++] = j;
            for (int s = 0; s < cnt; s++) {
                int m = lst[s];
                if (m != i && m != j) sl[sc2++] = m;
            }
            d_scnt[p] = sc2;
            for (int s = 0; s < 12; s++) d_slist[p][s] = (s < sc2) ? sl[s] : sl[0];
        }
        if (t < BB) {
            int bp = t * PP + p;
            d_rowq[bp*2 + 0] = bp*NN + i;
            d_rowq[bp*2 + 1] = bp*NN + j;
        }
        if (bid == 0 && t < NN) {
            d_deg[t] = sdeg[t];
            for (int s = 0; s < sdeg[t]; s++) d_nbrs[t][s] = snbrs[t][s];
        }
    } else if (bid < PP + 16) {
        int e0 = (bid - PP) * 16;
        for (int e = e0; e < e0 + 16; e++)
            d_WkT[e*256 + t] = Wk1[t*256 + e];
    } else {
        float acc = bo0[t];
        for (int k = 0; k < 256; k++) acc += bv0[k] * Wo0[k*256 + t];
        d_cvec[t] = acc;
    }
}

// ---------------- mma / cp.async helpers ----------------
__device__ __forceinline__ void mma_tf32(float* c, const unsigned* a, const unsigned* b) {
    asm volatile("mma.sync.aligned.m16n8k8.row.col.f32.tf32.tf32.f32 "
        "{%0,%1,%2,%3}, {%4,%5,%6,%7}, {%8,%9}, {%0,%1,%2,%3};"
        : "+f"(c[0]), "+f"(c[1]), "+f"(c[2]), "+f"(c[3])
        : "r"(a[0]), "r"(a[1]), "r"(a[2]), "r"(a[3]), "r"(b[0]), "r"(b[1]));
}
__device__ __forceinline__ void cp16(unsigned s, const float* g) {
    asm volatile("cp.async.cg.shared.global [%0], [%1], 16;" :: "r"(s), "l"(g));
}
__device__ __forceinline__ void cp_commit() {
    asm volatile("cp.async.commit_group;");
}
template<int N> __device__ __forceinline__ void cp_wait() {
    asm volatile("cp.async.wait_group %0;" :: "n"(N));
}

// ---------------- wide tf32 GEMM core: 128x128 tile, K-chunk 16, double-buffered ----------------
__device__ __forceinline__ void mmt_core(
    const float* __restrict__ A, int lda, const int* __restrict__ rowmap,
    const float* __restrict__ B, int ldb, const float* __restrict__ bias,
    float* __restrict__ C, int ldc, int M, int K, int row0, int col0)
{
    __shared__ __align__(16) unsigned As[2][128][20];   // [buf][m][k], raw fp32 bits
    __shared__ __align__(16) unsigned Bs[2][16][136];   // [buf][k][n]
    __shared__ int rmap[128];
    int tid = threadIdx.x;
    int lane = tid & 31, wid = tid >> 5;
    int wm = wid & 3, wn = wid >> 2;          // 4 x 2 warp grid
    int gid = lane >> 2, tig = lane & 3;

    for (int r = tid; r < 128; r += 256) {
        int gi = row0 + r; if (gi > M - 1) gi = M - 1;
        rmap[r] = rowmap ? rowmap[gi] : gi;
    }
    __syncthreads();

    float acc[2][8][4];
#pragma unroll
    for (int mi = 0; mi < 2; mi++)
#pragma unroll
        for (int ni = 0; ni < 8; ni++)
#pragma unroll
            for (int q = 0; q < 4; q++) acc[mi][ni][q] = 0.f;

    int sar = tid >> 1, sak = (tid & 1) * 8;     // A: 128 rows x 16 k, 8 floats/thread
    const float* Abase = A + (size_t)rmap[sar] * lda + sak;
    int sbk = tid >> 4, sbn = (tid & 15) * 8;    // B: 16 k-rows x 128 cols, 8 floats/thread
    const float* Bbase = B + (size_t)sbk * ldb + col0 + sbn;

    unsigned aAddr[2], bAddr[2];
#pragma unroll
    for (int b = 0; b < 2; b++) {
        aAddr[b] = (unsigned)__cvta_generic_to_shared(&As[b][sar][sak]);
        bAddr[b] = (unsigned)__cvta_generic_to_shared(&Bs[b][sbk][sbn]);
    }

    int nc = K >> 4;
    // prologue: stage chunk 0 -> buf 0
    cp16(aAddr[0], Abase);       cp16(aAddr[0] + 16, Abase + 4);
    cp16(bAddr[0], Bbase);       cp16(bAddr[0] + 16, Bbase + 4);
    cp_commit();

    for (int c = 0; c < nc; c++) {
        int cur = c & 1;
        if (c + 1 < nc) {
            int nxt = cur ^ 1;
            const float* ga = Abase + (c + 1) * 16;
            const float* gb = Bbase + (size_t)(c + 1) * 16 * ldb;
            cp16(aAddr[nxt], ga);       cp16(aAddr[nxt] + 16, ga + 4);
            cp16(bAddr[nxt], gb);       cp16(bAddr[nxt] + 16, gb + 4);
            cp_commit();
            cp_wait<1>();
        } else {
            cp_wait<0>();
        }
        __syncthreads();
#pragma unroll
        for (int ks = 0; ks < 2; ks++) {
            int kc0 = ks*8 + tig, kc1 = kc0 + 4;
            unsigned af[2][4], bf[8][2];
#pragma unroll
            for (int mi = 0; mi < 2; mi++) {
                int r0 = wm*32 + mi*16 + gid;
                af[mi][0] = As[cur][r0][kc0];
                af[mi][1] = As[cur][r0 + 8][kc0];
                af[mi][2] = As[cur][r0][kc1];
                af[mi][3] = As[cur][r0 + 8][kc1];
            }
#pragma unroll
            for (int ni = 0; ni < 8; ni++) {
                int n = wn*64 + ni*8 + gid;
                bf[ni][0] = Bs[cur][kc0][n];
                bf[ni][1] = Bs[cur][kc1][n];
            }
#pragma unroll
            for (int mi = 0; mi < 2; mi++)
#pragma unroll
                for (int ni = 0; ni < 8; ni++)
                    mma_tf32(acc[mi][ni], af[mi], bf[ni]);
        }
        __syncthreads();
    }

#pragma unroll
    for (int mi = 0; mi < 2; mi++) {
#pragma unroll
        for (int half = 0; half < 2; half++) {
            int gr = row0 + wm*32 + mi*16 + gid + half*8;
            if (gr >= M) continue;
#pragma unroll
            for (int ni = 0; ni < 8; ni++) {
                int gc = col0 + wn*64 + ni*8 + tig*2;
                float v0 = acc[mi][ni][half*2 + 0];
                float v1 = acc[mi][ni][half*2 + 1];
                if (bias) { v0 += __ldg(&bias[gc]); v1 += __ldg(&bias[gc + 1]); }
                float2 o; o.x = v0; o.y = v1;
                *(float2*)&C[(size_t)gr * ldc + gc] = o;
            }
        }
    }
}

// wrappers
__global__ void __launch_bounds__(256) k_qkv(const float* __restrict__ x,
    const float* __restrict__ Wq, const float* __restrict__ Wk, const float* __restrict__ Wv) {
    const float* B = (blockIdx.z == 0) ? Wq : (blockIdx.z == 1 ? Wk : Wv);
    mmt_core(x, 256, nullptr, B, 256, nullptr, d_XQKV + blockIdx.z*256, 768,
             BPTOT, 256, blockIdx.x*128, blockIdx.y*128);
}
__global__ void __launch_bounds__(256) k_yv(const float* __restrict__ Wo0) {
    int h = blockIdx.z;
    mmt_core(d_XQKV + 512 + h*32, 768, nullptr, Wo0 + h*8192, 256, nullptr,
             d_YV + h*256, 2048, BPTOT, 32, blockIdx.x*128, blockIdx.y*128);
}
__global__ void __launch_bounds__(256) k_q2(const float* __restrict__ Wq1, const float* __restrict__ bq1) {
    mmt_core(d_E2, 256, d_rowq, Wq1, 256, bq1, d_Q2, 256,
             NQ, 256, blockIdx.x*128, blockIdx.y*128);
}
__global__ void __launch_bounds__(256) k_u() {
    int h = blockIdx.z;
    mmt_core(d_Q2 + h*32, 256, nullptr, d_WkT + h*32*256, 256, nullptr,
             d_U + h*256, 2048, NQ, 32, blockIdx.x*128, blockIdx.y*128);
}
__global__ void __launch_bounds__(256) k_z2(const float* __restrict__ Wo1, const float* __restrict__ bo1) {
    mmt_core(d_att, 256, nullptr, Wo1, 256, bo1, d_Z2, 256,
             NQ, 256, blockIdx.x*128, blockIdx.y*128);
}

// ---------------- narrow tf32 GEMM (N=32), double-buffered: att_h = Zz_h @ Wv_h + bv_h ----------------
__global__ void __launch_bounds__(256) k_att(const float* __restrict__ Wv1,
                                             const float* __restrict__ bv1) {
    __shared__ __align__(16) unsigned As[2][128][20];
    __shared__ __align__(16) unsigned Bs[2][16][40];
    int h = blockIdx.y;
    int row0 = blockIdx.x * 128;
    const float* A = d_Zz + h*256;       // lda 2048
    const float* B = Wv1 + h*32;         // ldb 256
    int tid = threadIdx.x, lane = tid & 31, wid = tid >> 5;
    int gid = lane >> 2, tig = lane & 3;

    float acc[4][4];
#pragma unroll
    for (int ni = 0; ni < 4; ni++)
#pragma unroll
        for (int q = 0; q < 4; q++) acc[ni][q] = 0.f;

    int sar = tid >> 1, sak = (tid & 1) * 8;
    int arow = row0 + sar; if (arow > NQ - 1) arow = NQ - 1;
    const float* Abase = A + (size_t)arow * 2048 + sak;
    // B: 16 k-rows x 32 cols = 512 floats; threads 0..127 stage one float4 each
    int sbk = tid >> 3, sbc = (tid & 7) * 4;
    const float* Bbase = B + (size_t)sbk * 256 + sbc;

    unsigned aAddr[2], bAddr[2];
#pragma unroll
    for (int b = 0; b < 2; b++) {
        aAddr[b] = (unsigned)__cvta_generic_to_shared(&As[b][sar][sak]);
        bAddr[b] = (unsigned)__cvta_generic_to_shared(&Bs[b][sbk][sbc]);
    }
    bool bstage = (tid < 128);

    cp16(aAddr[0], Abase);       cp16(aAddr[0] + 16, Abase + 4);
    if (bstage) cp16(bAddr[0], Bbase);
    cp_commit();

    for (int c = 0; c < 16; c++) {
        int cur = c & 1;
        if (c + 1 < 16) {
            int nxt = cur ^ 1;
            const float* ga = Abase + (c + 1) * 16;
            cp16(aAddr[nxt], ga);       cp16(aAddr[nxt] + 16, ga + 4);
            if (bstage) cp16(bAddr[nxt], Bbase + (size_t)(c + 1) * 16 * 256);
            cp_commit();
            cp_wait<1>();
        } else {
            cp_wait<0>();
        }
        __syncthreads();
#pragma unroll
        for (int ks = 0; ks < 2; ks++) {
            int kc0 = ks*8 + tig, kc1 = kc0 + 4;
            int r0 = wid*16 + gid;
            unsigned af[4];
            af[0] = As[cur][r0][kc0]; af[1] = As[cur][r0 + 8][kc0];
            af[2] = As[cur][r0][kc1]; af[3] = As[cur][r0 + 8][kc1];
#pragma unroll
            for (int ni = 0; ni < 4; ni++) {
                unsigned bf[2];
                bf[0] = Bs[cur][kc0][ni*8 + gid];
                bf[1] = Bs[cur][kc1][ni*8 + gid];
                mma_tf32(acc[ni], af, bf);
            }
        }
        __syncthreads();
    }
#pragma unroll
    for (int half = 0; half < 2; half++) {
        int gr = row0 + wid*16 + gid + half*8;
        if (gr >= NQ) continue;
#pragma unroll
        for (int ni = 0; ni < 4; ni++) {
            int gc = ni*8 + tig*2;
            float v0 = acc[ni][half*2 + 0] + __ldg(&bv1[h*32 + gc]);
            float v1 = acc[ni][half*2 + 1] + __ldg(&bv1[h*32 + gc + 1]);
            float2 o; o.x = v0; o.y = v1;
            *(float2*)&d_att[(size_t)gr*256 + h*32 + gc] = o;
        }
    }
}

// ---------------- layer-1 attention (collapsed) + E2: 3-phase LN, warp-per-node reduce ----------------
__global__ void __launch_bounds__(256) k_attn1(
    const float* __restrict__ x,
    const float* __restrict__ bq0, const float* __restrict__ bk0,
    const float* __restrict__ g0, const float* __restrict__ b0)
{
    int bp = blockIdx.x;
    int p = bp % PP;
    int i = p / NN, j = p % NN;
    int tid = threadIdx.x;
    int w = tid >> 5, l = tid & 31;
    __shared__ float sA[8], sBq[8], sBk[8], sC[8];
    __shared__ float ssc[NN][8];
    __shared__ float sv[10][256];      // scn <= 10 (2 nodes + up to 8 neighbors)
    __shared__ float smu[10], srs[10];

    // per-head scalars: A = xq_h.xk_h, Bq = xq_h.bk_h, Bk = bq_h.xk_h, C = bq_h.bk_h
    {
        int idx = w * 32 + l;
        float xq = d_XQKV[(size_t)bp*768 + idx];
        float xk = d_XQKV[(size_t)bp*768 + 256 + idx];
        float bqv = bq0[idx], bkv = bk0[idx];
        float a = xq * xk, bqd = xq * bkv, bkd = bqv * xk, c = bqv * bkv;
#pragma unroll
        for (int o = 16; o > 0; o >>= 1) {
            a   += __shfl_xor_sync(~0u, a, o);
            bqd += __shfl_xor_sync(~0u, bqd, o);
            bkd += __shfl_xor_sync(~0u, bkd, o);
            c   += __shfl_xor_sync(~0u, c, o);
        }
        if (l == 0) { sA[w] = a; sBq[w] = bqd; sBk[w] = bkd; sC[w] = c; }
    }
    __syncthreads();

    // c[n,h] = sum_m softmax_m(score) * a_m over neighbors of n
    if (tid < NN * 8) {
        int n = tid >> 3, h = tid & 7;
        float A = sA[h], Bq = sBq[h], Bk = sBk[h], C = sC[h];
        float an = (float)((n == i) + (n == j));
        int dg = d_deg[n];
        float scm[4], amv[4];
        float mx = -1e30f;
        for (int s = 0; s < dg; s++) {
            int m = d_nbrs[n][s];
            float am = (float)((m == i) + (m == j));
            float sv2 = INV_SQRT_HD * (an*am*A + an*Bq + am*Bk + C);
            scm[s] = sv2; amv[s] = am;
            mx = fmaxf(mx, sv2);
        }
        float den = 0.f, num = 0.f;
        for (int s = 0; s < dg; s++) {
            float e = __expf(scm[s] - mx);
            den += e; num += e * amv[s];
        }
        ssc[n][h] = num / den;
    }
    __syncthreads();

    // Phase A: v[si][d] = cvec + a_n*x + sum_h sc[n,h]*yv[h]  (park in smem)
    int d = tid;
    float xd = x[(size_t)bp*256 + d];
    float cv = d_cvec[d];
    float yv[8];
#pragma unroll
    for (int h = 0; h < 8; h++) yv[h] = d_YV[(size_t)bp*2048 + h*256 + d];
    float gd = g0[d], bd = b0[d];
    int scn = d_scnt[p];
    for (int si = 0; si < scn; si++) {
        int n = d_slist[p][si];
        float an = (float)((n == i) + (n == j));
        float v = cv + an * xd;
#pragma unroll
        for (int h = 0; h < 8; h++) v += ssc[n][h] * yv[h];
        sv[si][d] = v;
    }
    __syncthreads();

    // Phase B: warp-per-node LN statistics
    for (int si = w; si < scn; si += 8) {
        float s1 = 0.f, s2 = 0.f;
#pragma unroll
        for (int q = 0; q < 8; q++) {
            float t = sv[si][l + 32*q];
            s1 += t; s2 = fmaf(t, t, s2);
        }
#pragma unroll
        for (int o = 16; o > 0; o >>= 1) {
            s1 += __shfl_xor_sync(~0u, s1, o);
            s2 += __shfl_xor_sync(~0u, s2, o);
        }
        if (l == 0) {
            float mu = s1 * (1.f/256.f), m2 = s2 * (1.f/256.f);
            smu[si] = mu;
            srs[si] = rsqrtf(m2 - mu*mu + LN_EPS);
        }
    }
    __syncthreads();

    // Phase C: normalize + write
    for (int si = 0; si < scn; si++) {
        int n = d_slist[p][si];
        float mu = smu[si], rs = srs[si];
        d_E2[((size_t)bp*NN + n)*256 + d] = (sv[si][d] - mu) * rs * gd + bd;
    }
}

// ---------------- layer-2: scores via U, softmax, z = sum_m w*E2_m ----------------
__global__ void __launch_bounds__(256) k_score_z(const float* __restrict__ bk1) {
    int bp = blockIdx.x;
    int p = bp % PP;
    int tid = threadIdx.x;
    int w = tid >> 5, l = tid & 31;
    __shared__ __align__(16) float sEm[8][256];
    __shared__ float sw[2][8][4];

    {
        int m = d_mlist[p][w];
        const float4* src = (const float4*)(d_E2 + ((size_t)bp*NN + m)*256);
        float4* dst = (float4*)sEm[w];
        dst[l] = src[l];
        dst[l + 32] = src[l + 32];
    }
    __syncthreads();

    for (int task = w; task < 16; task += 8) {
        int t = task & 1, h = task >> 1;
        int row = bp*2 + t;
        float qv = d_Q2[(size_t)row*256 + h*32 + l];
        float qb = qv * bk1[h*32 + l];
#pragma unroll
        for (int o = 16; o > 0; o >>= 1) qb += __shfl_xor_sync(~0u, qb, o);
        float u[8];
        const float* Up = d_U + (size_t)row*2048 + h*256;
#pragma unroll
        for (int q = 0; q < 8; q++) u[q] = Up[q*32 + l];
        int dg = d_qdeg[p][t];
        float scs[4];
        for (int s = 0; s < dg; s++) {
            int slot = d_qslot[p][t][s];
            float dt = 0.f;
#pragma unroll
            for (int q = 0; q < 8; q++) dt += u[q] * sEm[slot][q*32 + l];
#pragma unroll
            for (int o = 16; o > 0; o >>= 1) dt += __shfl_xor_sync(~0u, dt, o);
            scs[s] = (dt + qb) * INV_SQRT_HD;
        }
        if (l == 0) {
            float mx = -1e30f;
            for (int s = 0; s < dg; s++) mx = fmaxf(mx, scs[s]);
            float e[4]; float den = 0.f;
            for (int s = 0; s < dg; s++) { e[s] = __expf(scs[s] - mx); den += e[s]; }
            for (int s = 0; s < 4; s++) sw[t][h][s] = (s < dg) ? e[s] / den : 0.f;
        }
    }
    __syncthreads();

    int d = tid;
#pragma unroll
    for (int t = 0; t < 2; t++) {
        int dg = d_qdeg[p][t];
        int sl[4]; float em[4];
#pragma unroll
        for (int s = 0; s < 4; s++) {
            sl[s] = d_qslot[p][t][s];
            em[s] = sEm[sl[s]][d];
        }
#pragma unroll
        for (int h = 0; h < 8; h++) {
            float acc = 0.f;
            for (int s = 0; s < dg; s++) acc += sw[t][h][s] * em[s];
            d_Zz[((size_t)(bp*2 + t)*8 + h)*256 + d] = acc;
        }
    }
}

// ---------------- final LN + readout (single barrier pair) ----------------
__global__ void __launch_bounds__(256) k_final(
    const float* __restrict__ x,
    const float* __restrict__ g1, const float* __restrict__ b1,
    float* __restrict__ out)
{
    int bp = blockIdx.x;
    int p = bp % PP;
    int i = p / NN, jn = p % NN;
    int tid = threadIdx.x, w = tid >> 5, l = tid & 31;
    __shared__ float red[8][4];
    int d = tid;
    float gd = g1[d], bd = b1[d];
    float vA = d_Z2[((size_t)bp*2 + 0)*256 + d] + d_E2[((size_t)bp*NN + i)*256 + d];
    float vB = d_Z2[((size_t)bp*2 + 1)*256 + d] + d_E2[((size_t)bp*NN + jn)*256 + d];
    float s1a = vA, s2a = vA*vA, s1b = vB, s2b = vB*vB;
#pragma unroll
    for (int o = 16; o > 0; o >>= 1) {
        s1a += __shfl_xor_sync(~0u, s1a, o);
        s2a += __shfl_xor_sync(~0u, s2a, o);
        s1b += __shfl_xor_sync(~0u, s1b, o);
        s2b += __shfl_xor_sync(~0u, s2b, o);
    }
    if (l == 0) { red[w][0] = s1a; red[w][1] = s2a; red[w][2] = s1b; red[w][3] = s2b; }
    __syncthreads();
    float t1a = 0.f, t2a = 0.f, t1b = 0.f, t2b = 0.f;
#pragma unroll
    for (int q = 0; q < 8; q++) {
        t1a += red[q][0]; t2a += red[q][1];
        t1b += red[q][2]; t2b += red[q][3];
    }
    float muA = t1a*(1.f/256.f), mA = t2a*(1.f/256.f);
    float muB = t1b*(1.f/256.f), mB = t2b*(1.f/256.f);
    float rsA = rsqrtf(mA - muA*muA + LN_EPS);
    float rsB = rsqrtf(mB - muB*muB + LN_EPS);
    float e3a = (vA - muA) * rsA * gd + bd;
    float e3b = (vB - muB) * rsB * gd + bd;
    out[(size_t)bp*256 + d] = 0.5f * (e3a + e3b) + x[(size_t)bp*256 + d];
}

// ---------------- launch ----------------
extern "C" void kernel_launch(void* const* d_in, const int* in_sizes, int n_in,
                              void* d_out, int out_size)
{
    const float* x   = (const float*)d_in[0];
    const float* adj = (const float*)d_in[1];
    const float* Wq  = (const float*)d_in[2];
    const float* bq  = (const float*)d_in[3];
    const float* Wk  = (const float*)d_in[4];
    const float* bk  = (const float*)d_in[5];
    const float* Wv  = (const float*)d_in[6];
    const float* bv  = (const float*)d_in[7];
    const float* Wo  = (const float*)d_in[8];
    const float* bo  = (const float*)d_in[9];
    const float* lg  = (const float*)d_in[10];
    const float* lb  = (const float*)d_in[11];
    float* out = (float*)d_out;

    k_setup<<<PP + 17, 256>>>(adj, Wk + 65536, bv, Wo, bo);

    k_qkv<<<dim3(46, 2, 3), 256>>>(x, Wq, Wk, Wv);
    k_yv<<<dim3(46, 2, 8), 256>>>(Wo);

    k_attn1<<<BPTOT, 256>>>(x, bq, bk, lg, lb);

    k_q2<<<dim3(91, 2), 256>>>(Wq + 65536, bq + 256);
    k_u<<<dim3(91, 2, 8), 256>>>();

    k_score_z<<<BPTOT, 256>>>(bk + 256);

    k_att<<<dim3(91, 8), 256>>>(Wv + 65536, bv + 256);
    k_z2<<<dim3(91, 2), 256>>>(Wo + 65536, bo + 256);

    k_final<<<BPTOT, 256>>>(x, lg + 256, lb + 256, out);
}